// round 4
// baseline (speedup 1.0000x reference)
#include <cuda_runtime.h>
#include <cuda_bf16.h>

#define TOKENS 16384
#define HIDDEN 2048
#define NEXP   128
#define NOUT   256   // 0..127 = original router, 128..255 = bvh router
#define TOPK   8
#define NCAND  32

#define BM 32
#define BK 16

// Scratch (no allocations allowed): transposed weights + fused logits
__device__ float g_wT[HIDDEN * NOUT];      // [h][n]  (2 MB)
__device__ float g_logits[TOKENS * NOUT];  // [t][n]  (16 MB)

typedef unsigned long long u64;
union F2U { float2 f2; u64 u; };

// d += a*b per fp32 lane (IEEE rn, bitwise == scalar fmaf per lane)
__device__ __forceinline__ void ffma2_acc(u64& d, u64 a, u64 b) {
    asm volatile("fma.rn.f32x2 %0, %1, %2, %0;" : "+l"(d) : "l"(a), "l"(b));
}
// d = a*b + c per lane
__device__ __forceinline__ u64 ffma2(u64 a, u64 b, u64 c) {
    u64 d;
    asm volatile("fma.rn.f32x2 %0, %1, %2, %3;" : "=l"(d) : "l"(a), "l"(b), "l"(c));
    return d;
}
// d = a + b per lane
__device__ __forceinline__ u64 fadd2(u64 a, u64 b) {
    u64 d;
    asm volatile("add.rn.f32x2 %0, %1, %2;" : "=l"(d) : "l"(a), "l"(b));
    return d;
}

// ---------------------------------------------------------------------------
// Kernel 0: transpose both routers' weights into [H][256]
// ---------------------------------------------------------------------------
__global__ void wtrans_kernel(const float* __restrict__ wo,
                              const float* __restrict__ wb) {
    int idx = blockIdx.x * blockDim.x + threadIdx.x;
    if (idx >= HIDDEN * NOUT) return;
    int h = idx / NOUT;
    int n = idx - h * NOUT;
    float v = (n < NEXP) ? wo[n * HIDDEN + h] : wb[(n - NEXP) * HIDDEN + h];
    g_wT[idx] = v;
}

// ---------------------------------------------------------------------------
// Kernel 1: fp32 GEMM, packed f32x2, BITWISE identical accumulation to the
// round-2 passing kernel: per-BK=16 block partial (ascending fmaf order) +
// Kahan-compensated merge after EVERY tile. Microtile 4 tokens x 8 cols
// (96 accumulator regs -> no spills). Block: 32 tokens x 256 outputs.
// ---------------------------------------------------------------------------
__global__ __launch_bounds__(256) void gemm_kernel(const float* __restrict__ x) {
    __shared__ float2 xs[BM][BK + 1];   // 32 x 17 float2, duplicated {v,v}, padded
    __shared__ float  ws[BK][NOUT];     // 16 x 256 (16 KB)

    const int tid = threadIdx.x;
    const int m0  = blockIdx.x * BM;
    const int tx  = tid & 31;   // 8 output cols = 4 packed pairs
    const int ty  = tid >> 5;   // warp id 0..7 -> 4 tokens each

    u64 acc2[4][4];   // packed Kahan sum
    u64 cmp2[4][4];   // packed Kahan compensation
    u64 bp2[4][4];    // packed per-tile block partial
#pragma unroll
    for (int i = 0; i < 4; ++i)
#pragma unroll
        for (int j = 0; j < 4; ++j) { acc2[i][j] = 0ull; cmp2[i][j] = 0ull; bp2[i][j] = 0ull; }

    F2U n1; n1.f2 = make_float2(-1.0f, -1.0f);
    const u64 neg1 = n1.u;

    const int xr = tid >> 2;          // 0..63 (only <32 used when tid<128)
    const int xk = (tid & 3) << 2;    // 0,4,8,12

    for (int k0 = 0; k0 < HIDDEN; k0 += BK) {
        // x tile: 32x16 floats; threads 0..127 load one float4 each, store dup'd
        if (tid < 128) {
            float4 xv = *(const float4*)&x[(size_t)(m0 + xr) * HIDDEN + k0 + xk];
            xs[xr][xk + 0] = make_float2(xv.x, xv.x);
            xs[xr][xk + 1] = make_float2(xv.y, xv.y);
            xs[xr][xk + 2] = make_float2(xv.z, xv.z);
            xs[xr][xk + 3] = make_float2(xv.w, xv.w);
        }
        // w tile: 16x256 floats = 1024 float4, 4 per thread, coalesced
#pragma unroll
        for (int i = 0; i < 4; ++i) {
            int f4 = tid + i * 256;
            int kk = f4 >> 6;            // 0..15
            int c4 = (f4 & 63) << 2;     // 0..252
            *(float4*)&ws[kk][c4] = *(const float4*)&g_wT[(size_t)(k0 + kk) * NOUT + c4];
        }
        __syncthreads();

#pragma unroll
        for (int k = 0; k < BK; ++k) {
            u64 xp[4];
#pragma unroll
            for (int i = 0; i < 4; ++i) {
                F2U u; u.f2 = xs[ty * 4 + i][k];    // LDS.64 broadcast {v,v}
                xp[i] = u.u;
            }
            ulonglong2 wa = *(const ulonglong2*)&ws[k][tx * 8];      // LDS.128
            ulonglong2 wb = *(const ulonglong2*)&ws[k][tx * 8 + 4];  // LDS.128
            u64 wp[4] = { wa.x, wa.y, wb.x, wb.y };
#pragma unroll
            for (int i = 0; i < 4; ++i)
#pragma unroll
                for (int j = 0; j < 4; ++j)
                    ffma2_acc(bp2[i][j], xp[i], wp[j]);
        }

        // Kahan merge every tile (cadence 16 == round-2 passing numerics).
        // y = bp - cmp; t = acc + y; cmp = (t - acc) - y; acc = t
        // (a-b realized as fma(b,-1,a): single-rounded, bitwise == sub.rn)
#pragma unroll
        for (int i = 0; i < 4; ++i)
#pragma unroll
            for (int j = 0; j < 4; ++j) {
                u64 y = ffma2(cmp2[i][j], neg1, bp2[i][j]);
                u64 t = fadd2(acc2[i][j], y);
                u64 d = ffma2(acc2[i][j], neg1, t);
                cmp2[i][j] = ffma2(y, neg1, d);
                acc2[i][j] = t;
                bp2[i][j] = 0ull;
            }
        __syncthreads();
    }

#pragma unroll
    for (int i = 0; i < 4; ++i) {
        size_t row = (size_t)(m0 + ty * 4 + i) * NOUT + tx * 8;
        F2U a0, a1, a2, a3;
        a0.u = acc2[i][0]; a1.u = acc2[i][1]; a2.u = acc2[i][2]; a3.u = acc2[i][3];
        *(float4*)&g_logits[row]     = make_float4(a0.f2.x, a0.f2.y, a1.f2.x, a1.f2.y);
        *(float4*)&g_logits[row + 4] = make_float4(a2.f2.x, a2.f2.y, a3.f2.x, a3.f2.y);
    }
}

// ---------------------------------------------------------------------------
// Precise fp32 exp (immune to --use_fast_math): Cody-Waite + Horner, ~1 ulp.
// ---------------------------------------------------------------------------
__device__ __forceinline__ float exp_precise(float xx) {
    float kf = rintf(xx * 1.4426950408889634f);
    float r  = fmaf(kf, -0.693145751953125f, xx);      // ln2_hi
    r = fmaf(kf, -1.42860676533018704e-06f, r);        // ln2_lo
    float p = 1.98412698412698413e-04f;
    p = fmaf(p, r, 1.38888888888888889e-03f);
    p = fmaf(p, r, 8.33333333333333333e-03f);
    p = fmaf(p, r, 4.16666666666666667e-02f);
    p = fmaf(p, r, 1.66666666666666667e-01f);
    p = fmaf(p, r, 0.5f);
    p = fmaf(p, r, 1.0f);
    p = fmaf(p, r, 1.0f);
    int ki = (int)kf;
    float scale = __int_as_float((ki + 127) << 23);    // exact 2^k
    return p * scale;
}

// ---------------------------------------------------------------------------
// Kernel 2: per-token routing. 1 block (128 threads) per token.
// ---------------------------------------------------------------------------
__device__ __forceinline__ float warpMax(float v) {
#pragma unroll
    for (int o = 16; o; o >>= 1) v = fmaxf(v, __shfl_xor_sync(0xffffffffu, v, o));
    return v;
}
__device__ __forceinline__ float warpSum(float v) {
#pragma unroll
    for (int o = 16; o; o >>= 1) v += __shfl_xor_sync(0xffffffffu, v, o);
    return v;
}

__global__ __launch_bounds__(128) void route_kernel(float* __restrict__ out) {
    const int t = blockIdx.x;
    const int e = threadIdx.x;
    const int wid = e >> 5;
    const int lane = e & 31;

    __shared__ float s4[4];
    __shared__ float sb[NEXP];
    __shared__ float cand_p[NCAND];
    __shared__ int   cand_e[NCAND];
    __shared__ float top_p[TOPK];
    __shared__ int   top_e[TOPK];

    float fl = g_logits[(size_t)t * NOUT + e];
    float bl = g_logits[(size_t)t * NOUT + NEXP + e];

    // ---- full softmax ----
    float wm = warpMax(fl);
    if (lane == 0) s4[wid] = wm;
    __syncthreads();
    float m1 = fmaxf(fmaxf(s4[0], s4[1]), fmaxf(s4[2], s4[3]));
    __syncthreads();
    float p = exp_precise(fl - m1);
    float wsum = warpSum(p);
    if (lane == 0) s4[wid] = wsum;
    __syncthreads();
    float s1 = s4[0] + s4[1] + s4[2] + s4[3];
    __syncthreads();
    float prob = __fdiv_rn(p, s1);
    out[(size_t)t * NEXP + e] = prob;

    // ---- bvh softmax ----
    wm = warpMax(bl);
    if (lane == 0) s4[wid] = wm;
    __syncthreads();
    float m2 = fmaxf(fmaxf(s4[0], s4[1]), fmaxf(s4[2], s4[3]));
    __syncthreads();
    float q = exp_precise(bl - m2);
    wsum = warpSum(q);
    if (lane == 0) s4[wid] = wsum;
    __syncthreads();
    float s2 = s4[0] + s4[1] + s4[2] + s4[3];
    float bprob = __fdiv_rn(q, s2);
    sb[e] = bprob;
    __syncthreads();

    // ---- rank by bvh prob (descending, ties -> lower index) ----
    int r = 0;
#pragma unroll 8
    for (int j = 0; j < NEXP; ++j) {
        float v = sb[j];
        r += (v > bprob) || (v == bprob && j < e);
    }
    if (r < NCAND) { cand_e[r] = e; cand_p[r] = prob; }
    __syncthreads();

    // ---- top-8 among 32 candidates by full prob ----
    if (e < NCAND) {
        float cp = cand_p[e];
        int r2 = 0;
#pragma unroll
        for (int j = 0; j < NCAND; ++j) {
            float v = cand_p[j];
            r2 += (v > cp) || (v == cp && j < e);
        }
        if (r2 < TOPK) { top_e[r2] = cand_e[e]; top_p[r2] = cp; }
    }
    __syncthreads();

    // ---- renormalize + write ----
    if (e == 0) {
        float s = 0.f;
#pragma unroll
        for (int k = 0; k < TOPK; ++k) s += top_p[k];
        float* ov = out + (size_t)TOKENS * NEXP + (size_t)t * TOPK;
        float* oi = out + (size_t)TOKENS * NEXP + (size_t)TOKENS * TOPK + (size_t)t * TOPK;
#pragma unroll
        for (int k = 0; k < TOPK; ++k) {
            ov[k] = __fdiv_rn(top_p[k], s);
            oi[k] = (float)top_e[k];
        }
    }
}

// ---------------------------------------------------------------------------
extern "C" void kernel_launch(void* const* d_in, const int* in_sizes, int n_in,
                              void* d_out, int out_size) {
    const float* x  = (const float*)d_in[0];   // [16384, 2048]
    const float* wo = (const float*)d_in[1];   // [128, 2048] original router
    const float* wb = (const float*)d_in[2];   // [128, 2048] bvh router
    float* out = (float*)d_out;

    wtrans_kernel<<<(HIDDEN * NOUT + 255) / 256, 256>>>(wo, wb);
    gemm_kernel<<<TOKENS / BM, 256>>>(x);
    route_kernel<<<TOKENS, 128>>>(out);
}

// round 5
// speedup vs baseline: 1.3058x; 1.3058x over previous
#include <cuda_runtime.h>
#include <cuda_bf16.h>

#define TOKENS 16384
#define HIDDEN 2048
#define NEXP   128
#define NOUT   256   // 0..127 = original router, 128..255 = bvh router
#define TOPK   8
#define NCAND  32

#define BM 32
#define BK 16
#define NTILES (HIDDEN / BK)   // 128

// Scratch (no allocations allowed): transposed weights + fused logits
__device__ float g_wT[HIDDEN * NOUT];      // [h][n]  (2 MB)
__device__ float g_logits[TOKENS * NOUT];  // [t][n]  (16 MB)

typedef unsigned long long u64;
union F2U { float2 f2; u64 u; };

// NOTE: non-volatile asm. These are pure ops; the compiler may reorder or CSE
// them, which cannot change the bitwise result of the dependency-ordered
// accumulation chains. Per-lane they are IEEE-rn, bitwise == scalar fmaf/add.
__device__ __forceinline__ void ffma2_acc(u64& d, u64 a, u64 b) {
    asm("fma.rn.f32x2 %0, %1, %2, %0;" : "+l"(d) : "l"(a), "l"(b));
}
__device__ __forceinline__ u64 ffma2(u64 a, u64 b, u64 c) {
    u64 d;
    asm("fma.rn.f32x2 %0, %1, %2, %3;" : "=l"(d) : "l"(a), "l"(b), "l"(c));
    return d;
}
__device__ __forceinline__ u64 fadd2(u64 a, u64 b) {
    u64 d;
    asm("add.rn.f32x2 %0, %1, %2;" : "=l"(d) : "l"(a), "l"(b));
    return d;
}

__device__ __forceinline__ void cp16(void* smem_dst, const void* gmem_src) {
    unsigned int ds = (unsigned int)__cvta_generic_to_shared(smem_dst);
    asm volatile("cp.async.cg.shared.global [%0], [%1], 16;" :: "r"(ds), "l"(gmem_src));
}

// ---------------------------------------------------------------------------
// Kernel 0: transpose both routers' weights into [H][256]
// ---------------------------------------------------------------------------
__global__ void wtrans_kernel(const float* __restrict__ wo,
                              const float* __restrict__ wb) {
    int idx = blockIdx.x * blockDim.x + threadIdx.x;
    if (idx >= HIDDEN * NOUT) return;
    int h = idx / NOUT;
    int n = idx - h * NOUT;
    float v = (n < NEXP) ? wo[n * HIDDEN + h] : wb[(n - NEXP) * HIDDEN + h];
    g_wT[idx] = v;
}

// ---------------------------------------------------------------------------
// Kernel 1: fp32 GEMM, packed f32x2, bitwise identical accumulation to the
// certified round-2 numerics: per-BK=16 block partial (ascending fmaf order)
// + Kahan merge after every tile. 4 tokens x 8 cols per thread.
// cp.async double-buffered pipeline, 1 sync per tile, 2 CTAs/SM pinned.
// ---------------------------------------------------------------------------
__global__ __launch_bounds__(256, 2) void gemm_kernel(const float* __restrict__ x) {
    __shared__ float2 xs[2][BM][BK + 1];   // duplicated {v,v}, padded rows
    __shared__ float  ws[2][BK][NOUT];     // 2 x 16 KB

    const int tid = threadIdx.x;
    const int m0  = blockIdx.x * BM;
    const int tx  = tid & 31;   // 8 output cols = 4 packed pairs
    const int ty  = tid >> 5;   // warp id 0..7 -> 4 tokens each

    u64 acc2[4][4];   // packed Kahan sum
    u64 cmp2[4][4];   // packed Kahan compensation
    u64 bp2[4][4];    // packed per-tile block partial
#pragma unroll
    for (int i = 0; i < 4; ++i)
#pragma unroll
        for (int j = 0; j < 4; ++j) { acc2[i][j] = 0ull; cmp2[i][j] = 0ull; bp2[i][j] = 0ull; }

    F2U n1; n1.f2 = make_float2(-1.0f, -1.0f);
    const u64 neg1 = n1.u;

    const int xr = tid >> 2;          // 0..63 (rows 0..31 active for tid<128)
    const int xk = (tid & 3) << 2;    // 0,4,8,12

    // ---- preload tile 0 ----
    {
#pragma unroll
        for (int i = 0; i < 4; ++i) {
            int f4 = tid + i * 256;
            int kk = f4 >> 6;
            int c4 = (f4 & 63) << 2;
            cp16(&ws[0][kk][c4], &g_wT[(size_t)kk * NOUT + c4]);
        }
        if (tid < 128) {
            float4 xv = *(const float4*)&x[(size_t)(m0 + xr) * HIDDEN + xk];
            xs[0][xr][xk + 0] = make_float2(xv.x, xv.x);
            xs[0][xr][xk + 1] = make_float2(xv.y, xv.y);
            xs[0][xr][xk + 2] = make_float2(xv.z, xv.z);
            xs[0][xr][xk + 3] = make_float2(xv.w, xv.w);
        }
        asm volatile("cp.async.commit_group;");
        asm volatile("cp.async.wait_group 0;");
    }
    __syncthreads();

    for (int t = 0; t < NTILES; ++t) {
        const int cur = t & 1;
        const int nxt = cur ^ 1;
        const bool has_next = (t < NTILES - 1);

        // issue next tile's loads before computing this one
        float4 xn = make_float4(0.f, 0.f, 0.f, 0.f);
        if (has_next) {
            const int k1 = (t + 1) * BK;
#pragma unroll
            for (int i = 0; i < 4; ++i) {
                int f4 = tid + i * 256;
                int kk = f4 >> 6;
                int c4 = (f4 & 63) << 2;
                cp16(&ws[nxt][kk][c4], &g_wT[(size_t)(k1 + kk) * NOUT + c4]);
            }
            asm volatile("cp.async.commit_group;");
            if (tid < 128)
                xn = *(const float4*)&x[(size_t)(m0 + xr) * HIDDEN + k1 + xk];
        }

        // ---- compute tile (16 k, ascending order == certified numerics) ----
#pragma unroll
        for (int k = 0; k < BK; ++k) {
            u64 xp[4];
#pragma unroll
            for (int i = 0; i < 4; ++i) {
                F2U u; u.f2 = xs[cur][ty * 4 + i][k];    // LDS.64 broadcast {v,v}
                xp[i] = u.u;
            }
            ulonglong2 wa = *(const ulonglong2*)&ws[cur][k][tx * 8];      // LDS.128
            ulonglong2 wbv = *(const ulonglong2*)&ws[cur][k][tx * 8 + 4]; // LDS.128
            u64 wp[4] = { wa.x, wa.y, wbv.x, wbv.y };
#pragma unroll
            for (int i = 0; i < 4; ++i)
#pragma unroll
                for (int j = 0; j < 4; ++j)
                    ffma2_acc(bp2[i][j], xp[i], wp[j]);
        }

        // ---- Kahan merge (cadence 16 == certified numerics) ----
#pragma unroll
        for (int i = 0; i < 4; ++i)
#pragma unroll
            for (int j = 0; j < 4; ++j) {
                u64 y = ffma2(cmp2[i][j], neg1, bp2[i][j]);
                u64 s = fadd2(acc2[i][j], y);
                u64 d = ffma2(acc2[i][j], neg1, s);
                cmp2[i][j] = ffma2(y, neg1, d);
                acc2[i][j] = s;
                bp2[i][j] = 0ull;
            }

        // stage next x tile, then close the pipeline stage
        if (has_next && tid < 128) {
            xs[nxt][xr][xk + 0] = make_float2(xn.x, xn.x);
            xs[nxt][xr][xk + 1] = make_float2(xn.y, xn.y);
            xs[nxt][xr][xk + 2] = make_float2(xn.z, xn.z);
            xs[nxt][xr][xk + 3] = make_float2(xn.w, xn.w);
        }
        asm volatile("cp.async.wait_group 0;");
        __syncthreads();
    }

#pragma unroll
    for (int i = 0; i < 4; ++i) {
        size_t row = (size_t)(m0 + ty * 4 + i) * NOUT + tx * 8;
        F2U a0, a1, a2, a3;
        a0.u = acc2[i][0]; a1.u = acc2[i][1]; a2.u = acc2[i][2]; a3.u = acc2[i][3];
        *(float4*)&g_logits[row]     = make_float4(a0.f2.x, a0.f2.y, a1.f2.x, a1.f2.y);
        *(float4*)&g_logits[row + 4] = make_float4(a2.f2.x, a2.f2.y, a3.f2.x, a3.f2.y);
    }
}

// ---------------------------------------------------------------------------
// Precise fp32 exp (immune to --use_fast_math): Cody-Waite + Horner, ~1 ulp.
// ---------------------------------------------------------------------------
__device__ __forceinline__ float exp_precise(float xx) {
    float kf = rintf(xx * 1.4426950408889634f);
    float r  = fmaf(kf, -0.693145751953125f, xx);      // ln2_hi
    r = fmaf(kf, -1.42860676533018704e-06f, r);        // ln2_lo
    float p = 1.98412698412698413e-04f;
    p = fmaf(p, r, 1.38888888888888889e-03f);
    p = fmaf(p, r, 8.33333333333333333e-03f);
    p = fmaf(p, r, 4.16666666666666667e-02f);
    p = fmaf(p, r, 1.66666666666666667e-01f);
    p = fmaf(p, r, 0.5f);
    p = fmaf(p, r, 1.0f);
    p = fmaf(p, r, 1.0f);
    int ki = (int)kf;
    float scale = __int_as_float((ki + 127) << 23);    // exact 2^k
    return p * scale;
}

// ---------------------------------------------------------------------------
// Kernel 2: per-token routing. 1 block (128 threads) per token.
// ---------------------------------------------------------------------------
__device__ __forceinline__ float warpMax(float v) {
#pragma unroll
    for (int o = 16; o; o >>= 1) v = fmaxf(v, __shfl_xor_sync(0xffffffffu, v, o));
    return v;
}
__device__ __forceinline__ float warpSum(float v) {
#pragma unroll
    for (int o = 16; o; o >>= 1) v += __shfl_xor_sync(0xffffffffu, v, o);
    return v;
}

__global__ __launch_bounds__(128) void route_kernel(float* __restrict__ out) {
    const int t = blockIdx.x;
    const int e = threadIdx.x;
    const int wid = e >> 5;
    const int lane = e & 31;

    __shared__ float s4[4];
    __shared__ float sb[NEXP];
    __shared__ float cand_p[NCAND];
    __shared__ int   cand_e[NCAND];
    __shared__ float top_p[TOPK];
    __shared__ int   top_e[TOPK];

    float fl = g_logits[(size_t)t * NOUT + e];
    float bl = g_logits[(size_t)t * NOUT + NEXP + e];

    // ---- full softmax ----
    float wm = warpMax(fl);
    if (lane == 0) s4[wid] = wm;
    __syncthreads();
    float m1 = fmaxf(fmaxf(s4[0], s4[1]), fmaxf(s4[2], s4[3]));
    __syncthreads();
    float p = exp_precise(fl - m1);
    float wsum = warpSum(p);
    if (lane == 0) s4[wid] = wsum;
    __syncthreads();
    float s1 = s4[0] + s4[1] + s4[2] + s4[3];
    __syncthreads();
    float prob = __fdiv_rn(p, s1);
    out[(size_t)t * NEXP + e] = prob;

    // ---- bvh softmax ----
    wm = warpMax(bl);
    if (lane == 0) s4[wid] = wm;
    __syncthreads();
    float m2 = fmaxf(fmaxf(s4[0], s4[1]), fmaxf(s4[2], s4[3]));
    __syncthreads();
    float q = exp_precise(bl - m2);
    wsum = warpSum(q);
    if (lane == 0) s4[wid] = wsum;
    __syncthreads();
    float s2 = s4[0] + s4[1] + s4[2] + s4[3];
    float bprob = __fdiv_rn(q, s2);
    sb[e] = bprob;
    __syncthreads();

    // ---- rank by bvh prob (descending, ties -> lower index) ----
    int r = 0;
#pragma unroll 8
    for (int j = 0; j < NEXP; ++j) {
        float v = sb[j];
        r += (v > bprob) || (v == bprob && j < e);
    }
    if (r < NCAND) { cand_e[r] = e; cand_p[r] = prob; }
    __syncthreads();

    // ---- top-8 among 32 candidates by full prob ----
    if (e < NCAND) {
        float cp = cand_p[e];
        int r2 = 0;
#pragma unroll
        for (int j = 0; j < NCAND; ++j) {
            float v = cand_p[j];
            r2 += (v > cp) || (v == cp && j < e);
        }
        if (r2 < TOPK) { top_e[r2] = cand_e[e]; top_p[r2] = cp; }
    }
    __syncthreads();

    // ---- renormalize + write ----
    if (e == 0) {
        float s = 0.f;
#pragma unroll
        for (int k = 0; k < TOPK; ++k) s += top_p[k];
        float* ov = out + (size_t)TOKENS * NEXP + (size_t)t * TOPK;
        float* oi = out + (size_t)TOKENS * NEXP + (size_t)TOKENS * TOPK + (size_t)t * TOPK;
#pragma unroll
        for (int k = 0; k < TOPK; ++k) {
            ov[k] = __fdiv_rn(top_p[k], s);
            oi[k] = (float)top_e[k];
        }
    }
}

// ---------------------------------------------------------------------------
extern "C" void kernel_launch(void* const* d_in, const int* in_sizes, int n_in,
                              void* d_out, int out_size) {
    const float* x  = (const float*)d_in[0];   // [16384, 2048]
    const float* wo = (const float*)d_in[1];   // [128, 2048] original router
    const float* wb = (const float*)d_in[2];   // [128, 2048] bvh router
    float* out = (float*)d_out;

    wtrans_kernel<<<(HIDDEN * NOUT + 255) / 256, 256>>>(wo, wb);
    gemm_kernel<<<TOKENS / BM, 256>>>(x);
    route_kernel<<<TOKENS, 128>>>(out);
}

// round 7
// speedup vs baseline: 1.8643x; 1.4277x over previous
#include <cuda_runtime.h>
#include <cuda_bf16.h>
#include <cstdint>

#define TOKENS 16384
#define HIDDEN 2048
#define NEXP   128
#define NOUT   256   // 0..127 = original router, 128..255 = bvh router
#define TOPK   8
#define NCAND  32
#define TAU_L  6e-5f // logit-space knife-edge threshold (~4x worst-case tensor err)

typedef unsigned long long u64;

// ---------------- scratch (no allocs allowed) ----------------
__device__ float g_wT[HIDDEN * NOUT];          // [h][n] fp32 (certified recompute)
__device__ float g_logits[TOKENS * NOUT];      // [t][n]
__device__ __nv_bfloat16 g_xpl0[TOKENS * HIDDEN];
__device__ __nv_bfloat16 g_xpl1[TOKENS * HIDDEN];
__device__ __nv_bfloat16 g_xpl2[TOKENS * HIDDEN];
__device__ __nv_bfloat16 g_wpl0[NOUT * HIDDEN];
__device__ __nv_bfloat16 g_wpl1[NOUT * HIDDEN];
__device__ __nv_bfloat16 g_wpl2[NOUT * HIDDEN];
__device__ int g_nflag;
__device__ int g_flags[TOKENS];

// ---------------- PTX helpers (baseline ISA only: sm_80-era) ----------------
__device__ __forceinline__ uint32_t smem_u32(const void* p) {
    uint32_t a;
    asm("{ .reg .u64 t; cvta.to.shared.u64 t, %1; cvt.u32.u64 %0, t; }" : "=r"(a) : "l"(p));
    return a;
}
__device__ __forceinline__ void cp16s(uint32_t saddr, const void* g) {
    asm volatile("cp.async.cg.shared.global [%0], [%1], 16;" :: "r"(saddr), "l"(g));
}
__device__ __forceinline__ void ldsm4(uint32_t* r, uint32_t a) {
    asm volatile("ldmatrix.sync.aligned.m8n8.x4.shared.b16 {%0,%1,%2,%3}, [%4];"
                 : "=r"(r[0]), "=r"(r[1]), "=r"(r[2]), "=r"(r[3]) : "r"(a));
}
__device__ __forceinline__ void mma16816(float* d, const uint32_t* a, const uint32_t* b) {
    asm volatile(
        "mma.sync.aligned.m16n8k16.row.col.f32.bf16.bf16.f32 "
        "{%0,%1,%2,%3}, {%4,%5,%6,%7}, {%8,%9}, {%0,%1,%2,%3};"
        : "+f"(d[0]), "+f"(d[1]), "+f"(d[2]), "+f"(d[3])
        : "r"(a[0]), "r"(a[1]), "r"(a[2]), "r"(a[3]), "r"(b[0]), "r"(b[1]));
}

// ---------------------------------------------------------------------------
// Kernel 0: fp32 transposed weights [h][256] (certified recompute path)
// ---------------------------------------------------------------------------
__global__ void wtrans_kernel(const float* __restrict__ wo,
                              const float* __restrict__ wb) {
    int idx = blockIdx.x * blockDim.x + threadIdx.x;
    if (idx >= HIDDEN * NOUT) return;
    int h = idx / NOUT;
    int n = idx - h * NOUT;
    g_wT[idx] = (n < NEXP) ? wo[n * HIDDEN + h] : wb[(n - NEXP) * HIDDEN + h];
}

// ---------------------------------------------------------------------------
// bf16 3-plane split: v = p0 + p1 + p2 (residual ~2^-26 * v)
// ---------------------------------------------------------------------------
__device__ __forceinline__ void split3(float v, __nv_bfloat16& a0, __nv_bfloat16& a1, __nv_bfloat16& a2) {
    a0 = __float2bfloat16(v);
    float r1 = v - __bfloat162float(a0);
    a1 = __float2bfloat16(r1);
    float r2 = r1 - __bfloat162float(a1);
    a2 = __float2bfloat16(r2);
}

__global__ void xsplit_kernel(const float* __restrict__ x) {
    size_t i4 = (size_t)blockIdx.x * 256 + threadIdx.x;   // float4 index
    float4 v = ((const float4*)x)[i4];
    __nv_bfloat16 a0[4], a1[4], a2[4];
    split3(v.x, a0[0], a1[0], a2[0]);
    split3(v.y, a0[1], a1[1], a2[1]);
    split3(v.z, a0[2], a1[2], a2[2]);
    split3(v.w, a0[3], a1[3], a2[3]);
    size_t e = i4 * 4;
    *(__nv_bfloat162*)&g_xpl0[e]     = __nv_bfloat162{a0[0], a0[1]};
    *(__nv_bfloat162*)&g_xpl0[e + 2] = __nv_bfloat162{a0[2], a0[3]};
    *(__nv_bfloat162*)&g_xpl1[e]     = __nv_bfloat162{a1[0], a1[1]};
    *(__nv_bfloat162*)&g_xpl1[e + 2] = __nv_bfloat162{a1[2], a1[3]};
    *(__nv_bfloat162*)&g_xpl2[e]     = __nv_bfloat162{a2[0], a2[1]};
    *(__nv_bfloat162*)&g_xpl2[e + 2] = __nv_bfloat162{a2[2], a2[3]};
}

__global__ void wsplit_kernel(const float* __restrict__ wo,
                              const float* __restrict__ wb) {
    size_t i4 = (size_t)blockIdx.x * 256 + threadIdx.x;   // float4 index over [256][2048]
    if (i4 >= (size_t)NOUT * HIDDEN / 4) return;
    int n = (int)(i4 / (HIDDEN / 4));
    int c4 = (int)(i4 % (HIDDEN / 4)) * 4;
    const float* src = (n < NEXP) ? &wo[(size_t)n * HIDDEN + c4]
                                  : &wb[(size_t)(n - NEXP) * HIDDEN + c4];
    float4 v = *(const float4*)src;
    __nv_bfloat16 a0[4], a1[4], a2[4];
    split3(v.x, a0[0], a1[0], a2[0]);
    split3(v.y, a0[1], a1[1], a2[1]);
    split3(v.z, a0[2], a1[2], a2[2]);
    split3(v.w, a0[3], a1[3], a2[3]);
    size_t e = (size_t)n * HIDDEN + c4;
    *(__nv_bfloat162*)&g_wpl0[e]     = __nv_bfloat162{a0[0], a0[1]};
    *(__nv_bfloat162*)&g_wpl0[e + 2] = __nv_bfloat162{a0[2], a0[3]};
    *(__nv_bfloat162*)&g_wpl1[e]     = __nv_bfloat162{a1[0], a1[1]};
    *(__nv_bfloat162*)&g_wpl1[e + 2] = __nv_bfloat162{a1[2], a1[3]};
    *(__nv_bfloat162*)&g_wpl2[e]     = __nv_bfloat162{a2[0], a2[1]};
    *(__nv_bfloat162*)&g_wpl2[e + 2] = __nv_bfloat162{a2[2], a2[3]};
}

__global__ void zflag_kernel() { g_nflag = 0; }

// ---------------------------------------------------------------------------
// HMMA GEMM (mma.sync m16n8k16 bf16, baseline ISA): CTA = 128 tok x 128 exp.
// 8 warps as 4(M) x 2(N); warp tile 32 x 64; 6 split products into fp32 acc.
// BK = 32 bf16 per stage; rows padded to 80 B -> conflict-free ldmatrix.
// Double-buffered cp.async pipeline.
// ---------------------------------------------------------------------------
#define ROWB   80
#define PLANE  (128 * ROWB)     // 10240 B per plane tile
#define STAGEB (6 * PLANE)      // 61440 B
#define NKB    (HIDDEN / 32)    // 64 stages

__global__ __launch_bounds__(256) void tc_gemm_kernel() {
    extern __shared__ char smem[];
    const uint32_t sbase = smem_u32(smem);

    const int tid    = threadIdx.x;
    const int lane   = tid & 31;
    const int wid    = tid >> 5;
    const int warp_m = wid & 3;     // 0..3 -> 32-token slab
    const int warp_n = wid >> 2;    // 0..1 -> 64-expert slab
    const int m0     = blockIdx.x * 128;
    const int n0     = blockIdx.y * 128;

    // global source row bases per plane (A: tokens, B: experts)
    const __nv_bfloat16* gsrc[6] = {
        g_xpl0 + (size_t)m0 * HIDDEN, g_xpl1 + (size_t)m0 * HIDDEN, g_xpl2 + (size_t)m0 * HIDDEN,
        g_wpl0 + (size_t)n0 * HIDDEN, g_wpl1 + (size_t)n0 * HIDDEN, g_wpl2 + (size_t)n0 * HIDDEN
    };

    float acc[2][8][4];
#pragma unroll
    for (int mf = 0; mf < 2; ++mf)
#pragma unroll
        for (int nf = 0; nf < 8; ++nf)
#pragma unroll
            for (int c = 0; c < 4; ++c) acc[mf][nf][c] = 0.f;

    // per-thread ldmatrix address components
    const int a_row = lane & 15;                 // M0/M1 rows, M2/M3 repeat
    const int a_col = (lane >> 4) << 3;          // +8 bf16 for M2/M3
    const int b_row = ((lane >> 4) & 1) * 8 + (lane & 7);
    const int b_col = ((lane >> 3) & 1) * 8;

    // ---- stage loader: 12 x cp.async 16B per thread ----
    auto load_stage = [&](int kb, uint32_t stage) {
#pragma unroll
        for (int i = 0; i < 12; ++i) {
            const int pl  = i >> 1;
            const int row = ((i & 1) << 6) + (tid >> 2);
            const int seg = tid & 3;
            cp16s(stage + pl * PLANE + row * ROWB + seg * 16,
                  gsrc[pl] + (size_t)row * HIDDEN + kb * 32 + seg * 8);
        }
        asm volatile("cp.async.commit_group;");
    };

    load_stage(0, sbase);

    for (int kb = 0; kb < NKB; ++kb) {
        const uint32_t cur = sbase + (kb & 1) * STAGEB;
        const bool has_next = (kb + 1 < NKB);
        if (has_next) load_stage(kb + 1, sbase + ((kb + 1) & 1) * STAGEB);
        if (has_next) asm volatile("cp.async.wait_group 1;");
        else          asm volatile("cp.async.wait_group 0;");
        __syncthreads();

#pragma unroll
        for (int s = 0; s < 2; ++s) {
            // A frags: 3 planes x 2 mfrags
            uint32_t af[3][2][4];
#pragma unroll
            for (int p = 0; p < 3; ++p)
#pragma unroll
                for (int mf = 0; mf < 2; ++mf) {
                    uint32_t addr = cur + p * PLANE
                                  + (warp_m * 32 + mf * 16 + a_row) * ROWB
                                  + (s * 16 + a_col) * 2;
                    ldsm4(af[p][mf], addr);
                }
            // B planes one at a time; products grouped by B plane
#pragma unroll
            for (int pb = 0; pb < 3; ++pb) {
                uint32_t bf[4][4];   // np -> {nf=2np: b0,b1, nf=2np+1: b0,b1}
#pragma unroll
                for (int np = 0; np < 4; ++np) {
                    uint32_t addr = cur + (3 + pb) * PLANE
                                  + (warp_n * 64 + np * 16 + b_row) * ROWB
                                  + (s * 16 + b_col) * 2;
                    ldsm4(bf[np], addr);
                }
                const int na = 3 - pb;   // pb0: a0,a1,a2 | pb1: a0,a1 | pb2: a0
#pragma unroll
                for (int pa = 0; pa < 3; ++pa) {
                    if (pa >= na) break;
#pragma unroll
                    for (int mf = 0; mf < 2; ++mf)
#pragma unroll
                        for (int nf = 0; nf < 8; ++nf)
                            mma16816(acc[mf][nf], af[pa][mf], &bf[nf >> 1][(nf & 1) * 2]);
                }
            }
        }
        __syncthreads();   // protect cur buffer before next-next stage overwrites
    }

    // ---- epilogue ----
#pragma unroll
    for (int mf = 0; mf < 2; ++mf)
#pragma unroll
        for (int nf = 0; nf < 8; ++nf) {
            const int row = m0 + warp_m * 32 + mf * 16 + (lane >> 2);
            const int col = n0 + warp_n * 64 + nf * 8 + (lane & 3) * 2;
            *(float2*)&g_logits[(size_t)row * NOUT + col] =
                make_float2(acc[mf][nf][0], acc[mf][nf][1]);
            *(float2*)&g_logits[(size_t)(row + 8) * NOUT + col] =
                make_float2(acc[mf][nf][2], acc[mf][nf][3]);
        }
}

// ---------------------------------------------------------------------------
// Certified recompute (bitwise == round-2 chain) for flagged tokens.
// ---------------------------------------------------------------------------
__global__ __launch_bounds__(256) void recompute_kernel(const float* __restrict__ x) {
    const int n = threadIdx.x;
    const int cnt = g_nflag;
    for (int i = blockIdx.x; i < cnt; i += gridDim.x) {
        const int t = g_flags[i];
        const float* xr = x + (size_t)t * HIDDEN;
        float acc = 0.f, cmp = 0.f;
        for (int kb = 0; kb < HIDDEN; kb += 16) {
            float bp = 0.f;
#pragma unroll
            for (int k = 0; k < 16; ++k)
                bp = fmaf(xr[kb + k], g_wT[(size_t)(kb + k) * NOUT + n], bp);
            float y = bp - cmp;
            float s = acc + y;
            cmp = (s - acc) - y;
            acc = s;
        }
        g_logits[(size_t)t * NOUT + n] = acc;
    }
}

// ---------------------------------------------------------------------------
// Routing (decision logic identical to certified rounds) + logit-margin audit.
// ---------------------------------------------------------------------------
__device__ __forceinline__ float exp_precise(float xx) {
    float kf = rintf(xx * 1.4426950408889634f);
    float r  = fmaf(kf, -0.693145751953125f, xx);
    r = fmaf(kf, -1.42860676533018704e-06f, r);
    float p = 1.98412698412698413e-04f;
    p = fmaf(p, r, 1.38888888888888889e-03f);
    p = fmaf(p, r, 8.33333333333333333e-03f);
    p = fmaf(p, r, 4.16666666666666667e-02f);
    p = fmaf(p, r, 1.66666666666666667e-01f);
    p = fmaf(p, r, 0.5f);
    p = fmaf(p, r, 1.0f);
    p = fmaf(p, r, 1.0f);
    int ki = (int)kf;
    return p * __int_as_float((ki + 127) << 23);
}
__device__ __forceinline__ float warpMax(float v) {
#pragma unroll
    for (int o = 16; o; o >>= 1) v = fmaxf(v, __shfl_xor_sync(0xffffffffu, v, o));
    return v;
}
__device__ __forceinline__ float warpSum(float v) {
#pragma unroll
    for (int o = 16; o; o >>= 1) v += __shfl_xor_sync(0xffffffffu, v, o);
    return v;
}

__device__ __forceinline__ void route_one(int t, float* __restrict__ out, bool do_flag) {
    const int e = threadIdx.x;
    const int wid = e >> 5;
    const int lane = e & 31;

    __shared__ float s4[4];
    __shared__ float sb[NEXP];
    __shared__ float bvhl[NEXP];       // bvh LOGIT by bvh-rank (for margins)
    __shared__ float cand_p[NCAND];
    __shared__ float cand_fl[NCAND];   // full LOGIT per candidate position
    __shared__ int   cand_e[NCAND];
    __shared__ float candl[NCAND];     // full LOGIT by cand-rank (for margins)
    __shared__ float top_p[TOPK];
    __shared__ int   top_e[TOPK];

    float fl = g_logits[(size_t)t * NOUT + e];
    float bl = g_logits[(size_t)t * NOUT + NEXP + e];

    // ---- full softmax ----
    float wm = warpMax(fl);
    if (lane == 0) s4[wid] = wm;
    __syncthreads();
    float m1 = fmaxf(fmaxf(s4[0], s4[1]), fmaxf(s4[2], s4[3]));
    __syncthreads();
    float p = exp_precise(fl - m1);
    float wsum = warpSum(p);
    if (lane == 0) s4[wid] = wsum;
    __syncthreads();
    float s1 = s4[0] + s4[1] + s4[2] + s4[3];
    __syncthreads();
    float prob = __fdiv_rn(p, s1);
    out[(size_t)t * NEXP + e] = prob;

    // ---- bvh softmax ----
    wm = warpMax(bl);
    if (lane == 0) s4[wid] = wm;
    __syncthreads();
    float m2 = fmaxf(fmaxf(s4[0], s4[1]), fmaxf(s4[2], s4[3]));
    __syncthreads();
    float q = exp_precise(bl - m2);
    wsum = warpSum(q);
    if (lane == 0) s4[wid] = wsum;
    __syncthreads();
    float s2 = s4[0] + s4[1] + s4[2] + s4[3];
    float bprob = __fdiv_rn(q, s2);
    sb[e] = bprob;
    __syncthreads();

    // ---- rank by bvh prob (descending, ties -> lower index) ----
    int r = 0;
#pragma unroll 8
    for (int j = 0; j < NEXP; ++j) {
        float v = sb[j];
        r += (v > bprob) || (v == bprob && j < e);
    }
    bvhl[r] = bl;
    if (r < NCAND) { cand_e[r] = e; cand_p[r] = prob; cand_fl[r] = fl; }
    __syncthreads();

    // ---- top-8 among 32 candidates by full prob ----
    if (e < NCAND) {
        float cp = cand_p[e];
        int r2 = 0;
#pragma unroll
        for (int j = 0; j < NCAND; ++j) {
            float v = cand_p[j];
            r2 += (v > cp) || (v == cp && j < e);
        }
        candl[r2] = cand_fl[e];
        if (r2 < TOPK) { top_e[r2] = cand_e[e]; top_p[r2] = cp; }
    }
    __syncthreads();

    // ---- renormalize + write ----
    if (e == 0) {
        float s = 0.f;
#pragma unroll
        for (int k = 0; k < TOPK; ++k) s += top_p[k];
        float* ov = out + (size_t)TOKENS * NEXP + (size_t)t * TOPK;
        float* oi = out + (size_t)TOKENS * NEXP + (size_t)TOKENS * TOPK + (size_t)t * TOPK;
#pragma unroll
        for (int k = 0; k < TOPK; ++k) {
            ov[k] = __fdiv_rn(top_p[k], s);
            oi[k] = (float)top_e[k];
        }
        // ---- knife-edge audit: any decision margin (logit space) < TAU_L ----
        if (do_flag) {
            bool flag = (bvhl[NCAND - 1] - bvhl[NCAND] < TAU_L) ||
                        (candl[TOPK - 1] - candl[TOPK] < TAU_L);
#pragma unroll
            for (int k = 0; k < TOPK - 1; ++k)
                flag |= (candl[k] - candl[k + 1] < TAU_L);
            if (flag) {
                int pos = atomicAdd(&g_nflag, 1);
                g_flags[pos] = t;
            }
        }
    }
}

__global__ __launch_bounds__(128) void route_all_kernel(float* __restrict__ out) {
    route_one(blockIdx.x, out, true);
}
__global__ __launch_bounds__(128) void route_flagged_kernel(float* __restrict__ out) {
    const int cnt = g_nflag;
    for (int i = blockIdx.x; i < cnt; i += gridDim.x) {
        route_one(g_flags[i], out, false);
        __syncthreads();
    }
}

// ---------------------------------------------------------------------------
extern "C" void kernel_launch(void* const* d_in, const int* in_sizes, int n_in,
                              void* d_out, int out_size) {
    const float* x  = (const float*)d_in[0];   // [16384, 2048]
    const float* wo = (const float*)d_in[1];   // [128, 2048]
    const float* wb = (const float*)d_in[2];   // [128, 2048]
    float* out = (float*)d_out;

    cudaFuncSetAttribute(tc_gemm_kernel, cudaFuncAttributeMaxDynamicSharedMemorySize,
                         2 * STAGEB);

    wtrans_kernel<<<(HIDDEN * NOUT + 255) / 256, 256>>>(wo, wb);
    wsplit_kernel<<<(NOUT * HIDDEN / 4 + 255) / 256, 256>>>(wo, wb);
    xsplit_kernel<<<TOKENS * HIDDEN / 4 / 256, 256>>>(x);
    zflag_kernel<<<1, 1>>>();
    tc_gemm_kernel<<<dim3(TOKENS / 128, 2), 256, 2 * STAGEB>>>();
    route_all_kernel<<<TOKENS, 128>>>(out);
    recompute_kernel<<<1024, 256>>>(x);
    route_flagged_kernel<<<1024, 128>>>(out);
}

// round 8
// speedup vs baseline: 2.5322x; 1.3583x over previous
#include <cuda_runtime.h>
#include <cuda_bf16.h>
#include <cuda_fp16.h>
#include <cstdint>

#define TOKENS 16384
#define HIDDEN 2048
#define NEXP   128
#define NOUT   256   // 0..127 = original router, 128..255 = bvh router
#define TOPK   8
#define NCAND  32
#define TAU_L  6e-5f // logit-space knife-edge threshold (>>30x tensor error bound)

typedef unsigned long long u64;

// ---------------- scratch (no allocs allowed) ----------------
__device__ float g_wT[HIDDEN * NOUT];          // [h][n] fp32 (certified recompute)
__device__ float g_logits[TOKENS * NOUT];      // [t][n]
__device__ __half g_xp0[TOKENS * HIDDEN];
__device__ __half g_xp1[TOKENS * HIDDEN];
__device__ __half g_wp0[NOUT * HIDDEN];
__device__ __half g_wp1[NOUT * HIDDEN];
__device__ int g_nflag;
__device__ int g_flags[TOKENS];

// ---------------- PTX helpers (baseline ISA only) ----------------
__device__ __forceinline__ uint32_t smem_u32(const void* p) {
    uint32_t a;
    asm("{ .reg .u64 t; cvta.to.shared.u64 t, %1; cvt.u32.u64 %0, t; }" : "=r"(a) : "l"(p));
    return a;
}
__device__ __forceinline__ void cp16s(uint32_t saddr, const void* g) {
    asm volatile("cp.async.cg.shared.global [%0], [%1], 16;" :: "r"(saddr), "l"(g));
}
__device__ __forceinline__ void ldsm4(uint32_t* r, uint32_t a) {
    asm volatile("ldmatrix.sync.aligned.m8n8.x4.shared.b16 {%0,%1,%2,%3}, [%4];"
                 : "=r"(r[0]), "=r"(r[1]), "=r"(r[2]), "=r"(r[3]) : "r"(a));
}
__device__ __forceinline__ void mma16816(float* d, const uint32_t* a, const uint32_t* b) {
    asm volatile(
        "mma.sync.aligned.m16n8k16.row.col.f32.f16.f16.f32 "
        "{%0,%1,%2,%3}, {%4,%5,%6,%7}, {%8,%9}, {%0,%1,%2,%3};"
        : "+f"(d[0]), "+f"(d[1]), "+f"(d[2]), "+f"(d[3])
        : "r"(a[0]), "r"(a[1]), "r"(a[2]), "r"(a[3]), "r"(b[0]), "r"(b[1]));
}

// ---------------------------------------------------------------------------
// Kernel 0: fp32 transposed weights [h][256] (certified recompute path)
// ---------------------------------------------------------------------------
__global__ void wtrans_kernel(const float* __restrict__ wo,
                              const float* __restrict__ wb) {
    int idx = blockIdx.x * blockDim.x + threadIdx.x;
    if (idx >= HIDDEN * NOUT) return;
    int h = idx / NOUT;
    int n = idx - h * NOUT;
    g_wT[idx] = (n < NEXP) ? wo[n * HIDDEN + h] : wb[(n - NEXP) * HIDDEN + h];
}

// ---------------------------------------------------------------------------
// fp16 2-plane split: v = p0 + p1 + O(2^-22 v)
// ---------------------------------------------------------------------------
__device__ __forceinline__ void split2(float v, __half& a0, __half& a1) {
    a0 = __float2half_rn(v);
    a1 = __float2half_rn(v - __half2float(a0));
}

__global__ void xsplit_kernel(const float* __restrict__ x) {
    size_t i4 = (size_t)blockIdx.x * 256 + threadIdx.x;   // float4 index
    float4 v = ((const float4*)x)[i4];
    __half a0[4], a1[4];
    split2(v.x, a0[0], a1[0]);
    split2(v.y, a0[1], a1[1]);
    split2(v.z, a0[2], a1[2]);
    split2(v.w, a0[3], a1[3]);
    size_t e = i4 * 4;
    *(__half2*)&g_xp0[e]     = __half2{a0[0], a0[1]};
    *(__half2*)&g_xp0[e + 2] = __half2{a0[2], a0[3]};
    *(__half2*)&g_xp1[e]     = __half2{a1[0], a1[1]};
    *(__half2*)&g_xp1[e + 2] = __half2{a1[2], a1[3]};
}

__global__ void wsplit_kernel(const float* __restrict__ wo,
                              const float* __restrict__ wb) {
    size_t i4 = (size_t)blockIdx.x * 256 + threadIdx.x;   // float4 over [256][2048]
    if (blockIdx.x == 0 && threadIdx.x == 0) g_nflag = 0;
    if (i4 >= (size_t)NOUT * HIDDEN / 4) return;
    int n = (int)(i4 / (HIDDEN / 4));
    int c4 = (int)(i4 % (HIDDEN / 4)) * 4;
    const float* src = (n < NEXP) ? &wo[(size_t)n * HIDDEN + c4]
                                  : &wb[(size_t)(n - NEXP) * HIDDEN + c4];
    float4 v = *(const float4*)src;
    __half a0[4], a1[4];
    split2(v.x, a0[0], a1[0]);
    split2(v.y, a0[1], a1[1]);
    split2(v.z, a0[2], a1[2]);
    split2(v.w, a0[3], a1[3]);
    size_t e = (size_t)n * HIDDEN + c4;
    *(__half2*)&g_wp0[e]     = __half2{a0[0], a0[1]};
    *(__half2*)&g_wp0[e + 2] = __half2{a0[2], a0[3]};
    *(__half2*)&g_wp1[e]     = __half2{a1[0], a1[1]};
    *(__half2*)&g_wp1[e + 2] = __half2{a1[2], a1[3]};
}

// ---------------------------------------------------------------------------
// HMMA GEMM (mma.sync m16n8k16 f16): CTA = 128 tok x 128 exp, 8 warps 4x2.
// 3 split products (a0b0, a0b1, a1b0) into fp32 accumulators.
// BK = 32 halves per stage; rows padded to 80 B -> conflict-free ldmatrix.
// Double-buffered cp.async, 2 CTAs/SM -> all 256 CTAs in one wave.
// ---------------------------------------------------------------------------
#define ROWB   80
#define PLANE  (128 * ROWB)     // 10240 B
#define STAGEB (4 * PLANE)      // 40960 B
#define NKB    (HIDDEN / 32)    // 64 stages

__global__ __launch_bounds__(256, 2) void tc_gemm_kernel() {
    extern __shared__ char smem[];
    const uint32_t sbase = smem_u32(smem);

    const int tid    = threadIdx.x;
    const int lane   = tid & 31;
    const int wid    = tid >> 5;
    const int warp_m = wid & 3;
    const int warp_n = wid >> 2;
    const int m0     = blockIdx.x * 128;
    const int n0     = blockIdx.y * 128;

    const __half* gsrc[4] = {
        g_xp0 + (size_t)m0 * HIDDEN, g_xp1 + (size_t)m0 * HIDDEN,
        g_wp0 + (size_t)n0 * HIDDEN, g_wp1 + (size_t)n0 * HIDDEN
    };

    float acc[2][8][4];
#pragma unroll
    for (int mf = 0; mf < 2; ++mf)
#pragma unroll
        for (int nf = 0; nf < 8; ++nf)
#pragma unroll
            for (int c = 0; c < 4; ++c) acc[mf][nf][c] = 0.f;

    const int a_row = lane & 15;
    const int a_col = (lane >> 4) << 3;
    const int b_row = ((lane >> 4) & 1) * 8 + (lane & 7);
    const int b_col = ((lane >> 3) & 1) * 8;

    auto load_stage = [&](int kb, uint32_t stage) {
#pragma unroll
        for (int i = 0; i < 8; ++i) {
            const int pl  = i >> 1;
            const int row = ((i & 1) << 6) + (tid >> 2);
            const int seg = tid & 3;
            cp16s(stage + pl * PLANE + row * ROWB + seg * 16,
                  gsrc[pl] + (size_t)row * HIDDEN + kb * 32 + seg * 8);
        }
        asm volatile("cp.async.commit_group;");
    };

    load_stage(0, sbase);

    for (int kb = 0; kb < NKB; ++kb) {
        const uint32_t cur = sbase + (kb & 1) * STAGEB;
        const bool has_next = (kb + 1 < NKB);
        if (has_next) load_stage(kb + 1, sbase + ((kb + 1) & 1) * STAGEB);
        if (has_next) asm volatile("cp.async.wait_group 1;");
        else          asm volatile("cp.async.wait_group 0;");
        __syncthreads();

#pragma unroll
        for (int s = 0; s < 2; ++s) {
            uint32_t af[2][2][4];   // plane (a0,a1) x mfrag
#pragma unroll
            for (int p = 0; p < 2; ++p)
#pragma unroll
                for (int mf = 0; mf < 2; ++mf) {
                    uint32_t addr = cur + p * PLANE
                                  + (warp_m * 32 + mf * 16 + a_row) * ROWB
                                  + (s * 16 + a_col) * 2;
                    ldsm4(af[p][mf], addr);
                }
#pragma unroll
            for (int pb = 0; pb < 2; ++pb) {
                uint32_t bf[4][4];
#pragma unroll
                for (int np = 0; np < 4; ++np) {
                    uint32_t addr = cur + (2 + pb) * PLANE
                                  + (warp_n * 64 + np * 16 + b_row) * ROWB
                                  + (s * 16 + b_col) * 2;
                    ldsm4(bf[np], addr);
                }
                const int na = 2 - pb;   // pb0: a0,a1 | pb1: a0
#pragma unroll
                for (int pa = 0; pa < 2; ++pa) {
                    if (pa >= na) break;
#pragma unroll
                    for (int mf = 0; mf < 2; ++mf)
#pragma unroll
                        for (int nf = 0; nf < 8; ++nf)
                            mma16816(acc[mf][nf], af[pa][mf], &bf[nf >> 1][(nf & 1) * 2]);
                }
            }
        }
        __syncthreads();
    }

    // ---- epilogue ----
#pragma unroll
    for (int mf = 0; mf < 2; ++mf)
#pragma unroll
        for (int nf = 0; nf < 8; ++nf) {
            const int row = m0 + warp_m * 32 + mf * 16 + (lane >> 2);
            const int col = n0 + warp_n * 64 + nf * 8 + (lane & 3) * 2;
            *(float2*)&g_logits[(size_t)row * NOUT + col] =
                make_float2(acc[mf][nf][0], acc[mf][nf][1]);
            *(float2*)&g_logits[(size_t)(row + 8) * NOUT + col] =
                make_float2(acc[mf][nf][2], acc[mf][nf][3]);
        }
}

// ---------------------------------------------------------------------------
// Certified recompute (bitwise == round-2 chain) for flagged tokens.
// ---------------------------------------------------------------------------
__global__ __launch_bounds__(256) void recompute_kernel(const float* __restrict__ x) {
    const int n = threadIdx.x;
    const int cnt = g_nflag;
    for (int i = blockIdx.x; i < cnt; i += gridDim.x) {
        const int t = g_flags[i];
        const float* xr = x + (size_t)t * HIDDEN;
        float acc = 0.f, cmp = 0.f;
        for (int kb = 0; kb < HIDDEN; kb += 16) {
            float bp = 0.f;
#pragma unroll
            for (int k = 0; k < 16; ++k)
                bp = fmaf(xr[kb + k], g_wT[(size_t)(kb + k) * NOUT + n], bp);
            float y = bp - cmp;
            float s = acc + y;
            cmp = (s - acc) - y;
            acc = s;
        }
        g_logits[(size_t)t * NOUT + n] = acc;
    }
}

// ---------------------------------------------------------------------------
// Routing (decision logic identical to certified rounds) + logit-margin audit.
// ---------------------------------------------------------------------------
__device__ __forceinline__ float exp_precise(float xx) {
    float kf = rintf(xx * 1.4426950408889634f);
    float r  = fmaf(kf, -0.693145751953125f, xx);
    r = fmaf(kf, -1.42860676533018704e-06f, r);
    float p = 1.98412698412698413e-04f;
    p = fmaf(p, r, 1.38888888888888889e-03f);
    p = fmaf(p, r, 8.33333333333333333e-03f);
    p = fmaf(p, r, 4.16666666666666667e-02f);
    p = fmaf(p, r, 1.66666666666666667e-01f);
    p = fmaf(p, r, 0.5f);
    p = fmaf(p, r, 1.0f);
    p = fmaf(p, r, 1.0f);
    int ki = (int)kf;
    return p * __int_as_float((ki + 127) << 23);
}
__device__ __forceinline__ float warpMax(float v) {
#pragma unroll
    for (int o = 16; o; o >>= 1) v = fmaxf(v, __shfl_xor_sync(0xffffffffu, v, o));
    return v;
}
__device__ __forceinline__ float warpSum(float v) {
#pragma unroll
    for (int o = 16; o; o >>= 1) v += __shfl_xor_sync(0xffffffffu, v, o);
    return v;
}

__device__ __forceinline__ void route_one(int t, float* __restrict__ out, bool do_flag) {
    const int e = threadIdx.x;
    const int wid = e >> 5;
    const int lane = e & 31;

    __shared__ float s4[4];
    __shared__ float sb[NEXP];
    __shared__ float bvhl[NEXP];
    __shared__ float cand_p[NCAND];
    __shared__ float cand_fl[NCAND];
    __shared__ int   cand_e[NCAND];
    __shared__ float candl[NCAND];
    __shared__ float top_p[TOPK];
    __shared__ int   top_e[TOPK];

    float fl = g_logits[(size_t)t * NOUT + e];
    float bl = g_logits[(size_t)t * NOUT + NEXP + e];

    // ---- full softmax ----
    float wm = warpMax(fl);
    if (lane == 0) s4[wid] = wm;
    __syncthreads();
    float m1 = fmaxf(fmaxf(s4[0], s4[1]), fmaxf(s4[2], s4[3]));
    __syncthreads();
    float p = exp_precise(fl - m1);
    float wsum = warpSum(p);
    if (lane == 0) s4[wid] = wsum;
    __syncthreads();
    float s1 = s4[0] + s4[1] + s4[2] + s4[3];
    __syncthreads();
    float prob = __fdiv_rn(p, s1);
    out[(size_t)t * NEXP + e] = prob;

    // ---- bvh softmax ----
    wm = warpMax(bl);
    if (lane == 0) s4[wid] = wm;
    __syncthreads();
    float m2 = fmaxf(fmaxf(s4[0], s4[1]), fmaxf(s4[2], s4[3]));
    __syncthreads();
    float q = exp_precise(bl - m2);
    wsum = warpSum(q);
    if (lane == 0) s4[wid] = wsum;
    __syncthreads();
    float s2 = s4[0] + s4[1] + s4[2] + s4[3];
    float bprob = __fdiv_rn(q, s2);
    sb[e] = bprob;
    __syncthreads();

    // ---- rank by bvh prob (descending, ties -> lower index) ----
    int r = 0;
#pragma unroll 8
    for (int j = 0; j < NEXP; ++j) {
        float v = sb[j];
        r += (v > bprob) || (v == bprob && j < e);
    }
    bvhl[r] = bl;
    if (r < NCAND) { cand_e[r] = e; cand_p[r] = prob; cand_fl[r] = fl; }
    __syncthreads();

    // ---- top-8 among 32 candidates by full prob ----
    if (e < NCAND) {
        float cp = cand_p[e];
        int r2 = 0;
#pragma unroll
        for (int j = 0; j < NCAND; ++j) {
            float v = cand_p[j];
            r2 += (v > cp) || (v == cp && j < e);
        }
        candl[r2] = cand_fl[e];
        if (r2 < TOPK) { top_e[r2] = cand_e[e]; top_p[r2] = cp; }
    }
    __syncthreads();

    // ---- renormalize + write ----
    if (e == 0) {
        float s = 0.f;
#pragma unroll
        for (int k = 0; k < TOPK; ++k) s += top_p[k];
        float* ov = out + (size_t)TOKENS * NEXP + (size_t)t * TOPK;
        float* oi = out + (size_t)TOKENS * NEXP + (size_t)TOKENS * TOPK + (size_t)t * TOPK;
#pragma unroll
        for (int k = 0; k < TOPK; ++k) {
            ov[k] = __fdiv_rn(top_p[k], s);
            oi[k] = (float)top_e[k];
        }
        if (do_flag) {
            bool flag = (bvhl[NCAND - 1] - bvhl[NCAND] < TAU_L) ||
                        (candl[TOPK - 1] - candl[TOPK] < TAU_L);
#pragma unroll
            for (int k = 0; k < TOPK - 1; ++k)
                flag |= (candl[k] - candl[k + 1] < TAU_L);
            if (flag) {
                int pos = atomicAdd(&g_nflag, 1);
                g_flags[pos] = t;
            }
        }
    }
}

__global__ __launch_bounds__(128) void route_all_kernel(float* __restrict__ out) {
    route_one(blockIdx.x, out, true);
}
__global__ __launch_bounds__(128) void route_flagged_kernel(float* __restrict__ out) {
    const int cnt = g_nflag;
    for (int i = blockIdx.x; i < cnt; i += gridDim.x) {
        route_one(g_flags[i], out, false);
        __syncthreads();
    }
}

// ---------------------------------------------------------------------------
extern "C" void kernel_launch(void* const* d_in, const int* in_sizes, int n_in,
                              void* d_out, int out_size) {
    const float* x  = (const float*)d_in[0];   // [16384, 2048]
    const float* wo = (const float*)d_in[1];   // [128, 2048]
    const float* wb = (const float*)d_in[2];   // [128, 2048]
    float* out = (float*)d_out;

    cudaFuncSetAttribute(tc_gemm_kernel, cudaFuncAttributeMaxDynamicSharedMemorySize,
                         2 * STAGEB);

    wtrans_kernel<<<(HIDDEN * NOUT + 255) / 256, 256>>>(wo, wb);
    wsplit_kernel<<<(NOUT * HIDDEN / 4 + 255) / 256, 256>>>(wo, wb);
    xsplit_kernel<<<TOKENS * HIDDEN / 4 / 256, 256>>>(x);
    tc_gemm_kernel<<<dim3(TOKENS / 128, 2), 256, 2 * STAGEB>>>();
    route_all_kernel<<<TOKENS, 128>>>(out);
    recompute_kernel<<<1024, 256>>>(x);
    route_flagged_kernel<<<1024, 128>>>(out);
}